// round 1
// baseline (speedup 1.0000x reference)
#include <cuda_runtime.h>
#include <cuda_bf16.h>
#include <math.h>

#define NN 50000
#define EE 640000
#define GG 256
#define INC 32
#define HH 128
#define LL 5
#define LH 64
#define OUTC 10
#define EPS_GEN 1e-7f

// ---------------- scratch (static device globals; no runtime alloc) ----------
__device__ float g_h[NN * HH];        // node features
__device__ float g_xin[NN * HH];      // agg + h (GEMM1 input)
__device__ float g_hmid[NN * 2 * HH]; // GEMM1 out / BN+ReLU in-place
__device__ float g_hraw[NN * HH];     // GEMM2 out (pre-BN)
__device__ float g_cat[NN * 40];      // concat(x, ncc)
__device__ int   g_deg[NN];
__device__ int   g_cursor[NN];
__device__ int   g_rowstart[NN + 1];
__device__ int   g_csr[EE];           // packed (src<<2)|attr
__device__ float g_cstat[512 + 512];  // colsum[0:512], colsumsq[512:1024] (max M=256)
__device__ float g_p[GG * HH];        // pooled

// ---------------- utility kernels -------------------------------------------
__global__ void k_zero2_int(int* a, int* b, int n) {
    int i = blockIdx.x * blockDim.x + threadIdx.x;
    if (i < n) { a[i] = 0; b[i] = 0; }
}
__global__ void k_zero_f(float* a, int n) {
    int i = blockIdx.x * blockDim.x + threadIdx.x;
    if (i < n) a[i] = 0.f;
}

__global__ void k_hist(const int* __restrict__ dst) {
    int e = blockIdx.x * blockDim.x + threadIdx.x;
    if (e < EE) atomicAdd(&g_deg[dst[e]], 1);
}

// single-block exclusive scan of g_deg -> g_rowstart (N+1 entries)
__global__ void k_scan() {
    __shared__ int sh[1024];
    int t = threadIdx.x;
    int running = 0;
    for (int base = 0; base < NN; base += 1024) {
        int v = (base + t < NN) ? g_deg[base + t] : 0;
        sh[t] = v;
        __syncthreads();
        #pragma unroll
        for (int off = 1; off < 1024; off <<= 1) {
            int u = (t >= off) ? sh[t - off] : 0;
            __syncthreads();
            sh[t] += u;
            __syncthreads();
        }
        int incl = sh[t];
        if (base + t < NN) g_rowstart[base + t] = running + incl - v;
        int tot = sh[1023];
        __syncthreads();
        running += tot;
    }
    if (t == 0) g_rowstart[NN] = running;
}

__global__ void k_scatter(const int* __restrict__ src, const int* __restrict__ dst,
                          const int* __restrict__ attr) {
    int e = blockIdx.x * blockDim.x + threadIdx.x;
    if (e >= EE) return;
    int d = dst[e];
    int pos = atomicAdd(&g_cursor[d], 1);
    g_csr[g_rowstart[d] + pos] = (src[e] << 2) | (attr[e] & 3);
}

__global__ void k_cat(const float* __restrict__ x, const float* __restrict__ ncc) {
    int i = blockIdx.x * blockDim.x + threadIdx.x;
    if (i >= NN * 40) return;
    int n = i / 40, k = i - n * 40;
    g_cat[i] = (k < 32) ? x[n * 32 + k] : ncc[n * 8 + (k - 32)];
}

// ---------------- tiled fp32 GEMM: C[n,m] = sum_k A[n,k]*W[m,k] + bias[m] -----
#define BM 64
#define BN_ 64
#define BK 16
__global__ void k_gemm(const float* __restrict__ A, const float* __restrict__ W,
                       const float* __restrict__ bias, float* __restrict__ C,
                       int nrows, int M, int K) {
    __shared__ float As[BK][BM];
    __shared__ float Bs[BK][BN_];
    int tid = threadIdx.x;
    int tr = tid >> 4;        // 0..15
    int tc = tid & 15;        // 0..15
    int row0 = blockIdx.y * BM;
    int col0 = blockIdx.x * BN_;
    int lr = tid >> 2;        // 0..63
    int lk = (tid & 3) * 4;   // 0,4,8,12

    float acc[4][4];
    #pragma unroll
    for (int i = 0; i < 4; i++)
        #pragma unroll
        for (int j = 0; j < 4; j++) acc[i][j] = 0.f;

    for (int k0 = 0; k0 < K; k0 += BK) {
        // A tile
        {
            int r = row0 + lr;
            float v0 = 0.f, v1 = 0.f, v2 = 0.f, v3 = 0.f;
            if (r < nrows) {
                if (k0 + lk + 3 < K) {
                    float4 v = *(const float4*)&A[(size_t)r * K + k0 + lk];
                    v0 = v.x; v1 = v.y; v2 = v.z; v3 = v.w;
                } else {
                    if (k0 + lk + 0 < K) v0 = A[(size_t)r * K + k0 + lk + 0];
                    if (k0 + lk + 1 < K) v1 = A[(size_t)r * K + k0 + lk + 1];
                    if (k0 + lk + 2 < K) v2 = A[(size_t)r * K + k0 + lk + 2];
                    if (k0 + lk + 3 < K) v3 = A[(size_t)r * K + k0 + lk + 3];
                }
            }
            As[lk + 0][lr] = v0; As[lk + 1][lr] = v1;
            As[lk + 2][lr] = v2; As[lk + 3][lr] = v3;
        }
        // W tile
        {
            int c = col0 + lr;   // always < M (M multiple of 64)
            float v0 = 0.f, v1 = 0.f, v2 = 0.f, v3 = 0.f;
            if (k0 + lk + 3 < K) {
                float4 v = *(const float4*)&W[(size_t)c * K + k0 + lk];
                v0 = v.x; v1 = v.y; v2 = v.z; v3 = v.w;
            } else {
                if (k0 + lk + 0 < K) v0 = W[(size_t)c * K + k0 + lk + 0];
                if (k0 + lk + 1 < K) v1 = W[(size_t)c * K + k0 + lk + 1];
                if (k0 + lk + 2 < K) v2 = W[(size_t)c * K + k0 + lk + 2];
                if (k0 + lk + 3 < K) v3 = W[(size_t)c * K + k0 + lk + 3];
            }
            Bs[lk + 0][lr] = v0; Bs[lk + 1][lr] = v1;
            Bs[lk + 2][lr] = v2; Bs[lk + 3][lr] = v3;
        }
        __syncthreads();
        #pragma unroll
        for (int kk = 0; kk < BK; kk++) {
            float4 a = *(const float4*)&As[kk][tr * 4];
            float4 b = *(const float4*)&Bs[kk][tc * 4];
            float av[4] = {a.x, a.y, a.z, a.w};
            float bv[4] = {b.x, b.y, b.z, b.w};
            #pragma unroll
            for (int i = 0; i < 4; i++)
                #pragma unroll
                for (int j = 0; j < 4; j++)
                    acc[i][j] = fmaf(av[i], bv[j], acc[i][j]);
        }
        __syncthreads();
    }
    #pragma unroll
    for (int i = 0; i < 4; i++) {
        int r = row0 + tr * 4 + i;
        if (r >= nrows) continue;
        int c = col0 + tc * 4;
        float4 o;
        o.x = acc[i][0] + bias[c + 0];
        o.y = acc[i][1] + bias[c + 1];
        o.z = acc[i][2] + bias[c + 2];
        o.w = acc[i][3] + bias[c + 3];
        *(float4*)&C[(size_t)r * M + c] = o;
    }
}

// ---------------- column stats (sum, sumsq) over nrows ------------------------
__global__ void k_colstats(const float* __restrict__ C, int M) {
    int m = threadIdx.x;                  // blockDim.x == M
    float s = 0.f, q = 0.f;
    for (int r = blockIdx.x; r < NN; r += gridDim.x) {
        float v = C[(size_t)r * M + m];
        s += v; q += v * v;
    }
    atomicAdd(&g_cstat[m], s);
    atomicAdd(&g_cstat[512 + m], q);
}

__global__ void k_bnrelu(const float* __restrict__ X, float* __restrict__ Y,
                         const float* __restrict__ gam, const float* __restrict__ bet,
                         int M) {
    int i = blockIdx.x * blockDim.x + threadIdx.x;
    if (i >= NN * M) return;
    int m = i % M;
    float invN = 1.f / (float)NN;
    float mu = g_cstat[m] * invN;
    float var = g_cstat[512 + m] * invN - mu * mu;
    float v = (X[i] - mu) * rsqrtf(var + 1e-5f) * gam[m] + bet[m];
    Y[i] = v > 0.f ? v : 0.f;
}

// ---------------- fused edge aggregation: warp per node, online softmax -------
__global__ void k_agg(const float* __restrict__ h, const float* __restrict__ eemb,
                      float* __restrict__ out) {
    int warp = (blockIdx.x * blockDim.x + threadIdx.x) >> 5;
    int lane = threadIdx.x & 31;
    if (warp >= NN) return;
    int n = warp;
    int beg = g_rowstart[n], end = g_rowstart[n + 1];
    float m[4] = {-1e30f, -1e30f, -1e30f, -1e30f};
    float s[4] = {0.f, 0.f, 0.f, 0.f};
    float w[4] = {0.f, 0.f, 0.f, 0.f};
    int co = lane * 4;
    for (int j = beg; j < end; j++) {
        int p = __ldg(&g_csr[j]);
        int src = p >> 2;
        int a = p & 3;
        float4 hv = *(const float4*)&h[(size_t)src * HH + co];
        float4 ev = *(const float4*)&eemb[a * HH + co];
        float msg[4];
        msg[0] = fmaxf(hv.x + ev.x, 0.f) + EPS_GEN;
        msg[1] = fmaxf(hv.y + ev.y, 0.f) + EPS_GEN;
        msg[2] = fmaxf(hv.z + ev.z, 0.f) + EPS_GEN;
        msg[3] = fmaxf(hv.w + ev.w, 0.f) + EPS_GEN;
        #pragma unroll
        for (int c = 0; c < 4; c++) {
            if (msg[c] > m[c]) {
                float sc = __expf(m[c] - msg[c]);
                s[c] *= sc; w[c] *= sc; m[c] = msg[c];
            }
            float e = __expf(msg[c] - m[c]);
            s[c] += e;
            w[c] += e * msg[c];
        }
    }
    float4 hn = *(const float4*)&h[(size_t)n * HH + co];
    bool has = end > beg;
    float4 o;
    o.x = (has ? w[0] / s[0] : 0.f) + hn.x;
    o.y = (has ? w[1] / s[1] : 0.f) + hn.y;
    o.z = (has ? w[2] / s[2] : 0.f) + hn.z;
    o.w = (has ? w[3] / s[3] : 0.f) + hn.w;
    *(float4*)&out[(size_t)n * HH + co] = o;
}

// ---------------- pooling ------------------------------------------------------
__global__ void k_pool(const float* __restrict__ h, const int* __restrict__ batch) {
    int i = blockIdx.x * blockDim.x + threadIdx.x;
    if (i >= NN * 32) return;
    int n = i >> 5;
    int lane = i & 31;
    int g = batch[n];
    float4 v = *(const float4*)&h[(size_t)n * HH + lane * 4];
    float* dst = &g_p[(size_t)g * HH + lane * 4];
    atomicAdd(dst + 0, v.x);
    atomicAdd(dst + 1, v.y);
    atomicAdd(dst + 2, v.z);
    atomicAdd(dst + 3, v.w);
}

// ---------------- head: LSTM (1 step, h0=c0=0) + final linear ------------------
__device__ __forceinline__ float sigm(float x) { return 1.f / (1.f + __expf(-x)); }

__global__ void k_head(const float* __restrict__ wih, const float* __restrict__ bih,
                       const float* __restrict__ bhh, const float* __restrict__ linw,
                       const float* __restrict__ linb, float* __restrict__ out) {
    __shared__ float ps[HH];
    __shared__ float gs[4 * LH];
    __shared__ float hh[LH];
    int g = blockIdx.x;
    int t = threadIdx.x;       // 256 threads
    if (t < HH) ps[t] = g_p[(size_t)g * HH + t];
    __syncthreads();
    {
        float acc = bih[t] + bhh[t];
        const float* wr = &wih[(size_t)t * HH];
        #pragma unroll 8
        for (int k = 0; k < HH; k++) acc = fmaf(ps[k], wr[k], acc);
        gs[t] = acc;
    }
    __syncthreads();
    if (t < LH) {
        float ig = gs[t];
        float gg = gs[t + 2 * LH];
        float og = gs[t + 3 * LH];
        float c = sigm(ig) * tanhf(gg);
        hh[t] = sigm(og) * tanhf(c);
    }
    __syncthreads();
    if (t < OUTC) {
        float acc = linb[t];
        const float* wr = &linw[(size_t)t * LH];
        #pragma unroll
        for (int k = 0; k < LH; k++) acc = fmaf(hh[k], wr[k], acc);
        out[(size_t)g * OUTC + t] = acc;
    }
}

// ---------------- launch -------------------------------------------------------
extern "C" void kernel_launch(void* const* d_in, const int* in_sizes, int n_in,
                              void* d_out, int out_size) {
    const float* x        = (const float*)d_in[0];
    const float* ncc      = (const float*)d_in[1];
    const int*   eidx     = (const int*)d_in[2];
    const int*   eattr    = (const int*)d_in[3];
    const int*   batch    = (const int*)d_in[4];
    const float* fc_w     = (const float*)d_in[5];
    const float* fc_b     = (const float*)d_in[6];
    const float* edge_emb = (const float*)d_in[7];
    const float* conv_w1  = (const float*)d_in[8];
    const float* conv_b1  = (const float*)d_in[9];
    const float* cbn_g    = (const float*)d_in[10];
    const float* cbn_b    = (const float*)d_in[11];
    const float* conv_w2  = (const float*)d_in[12];
    const float* conv_b2  = (const float*)d_in[13];
    const float* bn_g     = (const float*)d_in[14];
    const float* bn_b     = (const float*)d_in[15];
    const float* lstm_wih = (const float*)d_in[16];
    const float* lstm_whh = (const float*)d_in[17];  // unused (h0 = 0)
    const float* lstm_bih = (const float*)d_in[18];
    const float* lstm_bhh = (const float*)d_in[19];
    const float* lin_w    = (const float*)d_in[20];
    const float* lin_b    = (const float*)d_in[21];
    (void)lstm_whh; (void)n_in; (void)in_sizes; (void)out_size;
    float* outp = (float*)d_out;

    const int* src = eidx;
    const int* dst = eidx + EE;

    int *p_deg, *p_cursor;
    float *p_h, *p_xin, *p_hmid, *p_hraw, *p_cat, *p_cstat, *p_pool;
    cudaGetSymbolAddress((void**)&p_deg, g_deg);
    cudaGetSymbolAddress((void**)&p_cursor, g_cursor);
    cudaGetSymbolAddress((void**)&p_h, g_h);
    cudaGetSymbolAddress((void**)&p_xin, g_xin);
    cudaGetSymbolAddress((void**)&p_hmid, g_hmid);
    cudaGetSymbolAddress((void**)&p_hraw, g_hraw);
    cudaGetSymbolAddress((void**)&p_cat, g_cat);
    cudaGetSymbolAddress((void**)&p_cstat, g_cstat);
    cudaGetSymbolAddress((void**)&p_pool, g_p);

    // --- CSR build ---
    k_zero2_int<<<(NN + 255) / 256, 256>>>(p_deg, p_cursor, NN);
    k_hist<<<(EE + 255) / 256, 256>>>(dst);
    k_scan<<<1, 1024>>>();
    k_scatter<<<(EE + 255) / 256, 256>>>(src, dst, eattr);

    // --- initial FC: h = concat(x,ncc) @ fc_w^T + fc_b ---
    k_cat<<<(NN * 40 + 255) / 256, 256>>>(x, ncc);
    {
        dim3 grid(HH / BN_, (NN + BM - 1) / BM);
        k_gemm<<<grid, 256>>>(p_cat, fc_w, fc_b, p_h, NN, HH, 40);
    }

    // --- layers ---
    for (int l = 0; l < LL; l++) {
        // edge aggregation + residual -> xin
        k_agg<<<(NN * 32 + 255) / 256, 256>>>(p_h, edge_emb, p_xin);

        // GEMM1: [N,128] x [256,128]^T -> [N,256]
        {
            dim3 grid((2 * HH) / BN_, (NN + BM - 1) / BM);
            k_gemm<<<grid, 256>>>(p_xin, conv_w1 + (size_t)l * 2 * HH * HH,
                                  conv_b1 + (size_t)l * 2 * HH, p_hmid, NN, 2 * HH, HH);
        }
        k_zero_f<<<4, 256>>>(p_cstat, 1024);
        k_colstats<<<256, 2 * HH>>>(p_hmid, 2 * HH);
        k_bnrelu<<<(NN * 2 * HH + 255) / 256, 256>>>(p_hmid, p_hmid,
                                                     cbn_g + (size_t)l * 2 * HH,
                                                     cbn_b + (size_t)l * 2 * HH, 2 * HH);

        // GEMM2: [N,256] x [128,256]^T -> [N,128]
        {
            dim3 grid(HH / BN_, (NN + BM - 1) / BM);
            k_gemm<<<grid, 256>>>(p_hmid, conv_w2 + (size_t)l * HH * 2 * HH,
                                  conv_b2 + (size_t)l * HH, p_hraw, NN, HH, 2 * HH);
        }
        k_zero_f<<<4, 256>>>(p_cstat, 1024);
        k_colstats<<<256, HH>>>(p_hraw, HH);
        k_bnrelu<<<(NN * HH + 255) / 256, 256>>>(p_hraw, p_h,
                                                 bn_g + (size_t)l * HH,
                                                 bn_b + (size_t)l * HH, HH);
    }

    // --- pool + head ---
    k_zero_f<<<(GG * HH + 255) / 256, 256>>>(p_pool, GG * HH);
    k_pool<<<(NN * 32 + 255) / 256, 256>>>(p_h, batch);
    k_head<<<GG, 256>>>(lstm_wih, lstm_bih, lstm_bhh, lin_w, lin_b, outp);
}

// round 2
// speedup vs baseline: 1.2058x; 1.2058x over previous
#include <cuda_runtime.h>
#include <cuda_bf16.h>
#include <math.h>

#define NN 50000
#define EE 640000
#define GG 256
#define INC 32
#define HH 128
#define LL 5
#define LH 64
#define OUTC 10
#define EPS_GEN 1e-7f

// ---------------- scratch (static device globals; no runtime alloc) ----------
__device__ float g_h[NN * HH];        // node features
__device__ float g_xin[NN * HH];      // agg + h (GEMM1 input)
__device__ float g_hmid[NN * 2 * HH]; // GEMM1 out (raw, pre-BN)
__device__ float g_hraw[NN * HH];     // GEMM2 out (pre-BN)
__device__ float g_cat[NN * 40];      // concat(x, ncc)
__device__ int   g_deg[NN];
__device__ int   g_cursor[NN];
__device__ int   g_rowstart[NN + 1];
__device__ int   g_csr[EE];           // packed (src<<2)|attr
__device__ float g_cstat[512 + 512];  // colsum[0:512], colsumsq[512:1024]
__device__ float g_ss[1024];          // BN scale[0:512], shift[512:1024]
__device__ float g_p[GG * HH];        // pooled

// ---------------- utility kernels -------------------------------------------
__global__ void k_zero2_int(int* a, int* b, int n) {
    int i = blockIdx.x * blockDim.x + threadIdx.x;
    if (i < n) { a[i] = 0; b[i] = 0; }
}
__global__ void k_zero_f(float* a, int n) {
    int i = blockIdx.x * blockDim.x + threadIdx.x;
    if (i < n) a[i] = 0.f;
}

__global__ void k_hist(const int* __restrict__ dst) {
    int e = blockIdx.x * blockDim.x + threadIdx.x;
    if (e < EE) atomicAdd(&g_deg[dst[e]], 1);
}

// single-block exclusive scan of g_deg -> g_rowstart (N+1 entries)
__global__ void k_scan() {
    __shared__ int sh[1024];
    int t = threadIdx.x;
    int running = 0;
    for (int base = 0; base < NN; base += 1024) {
        int v = (base + t < NN) ? g_deg[base + t] : 0;
        sh[t] = v;
        __syncthreads();
        #pragma unroll
        for (int off = 1; off < 1024; off <<= 1) {
            int u = (t >= off) ? sh[t - off] : 0;
            __syncthreads();
            sh[t] += u;
            __syncthreads();
        }
        int incl = sh[t];
        if (base + t < NN) g_rowstart[base + t] = running + incl - v;
        int tot = sh[1023];
        __syncthreads();
        running += tot;
    }
    if (t == 0) g_rowstart[NN] = running;
}

__global__ void k_scatter(const int* __restrict__ src, const int* __restrict__ dst,
                          const int* __restrict__ attr) {
    int e = blockIdx.x * blockDim.x + threadIdx.x;
    if (e >= EE) return;
    int d = dst[e];
    int pos = atomicAdd(&g_cursor[d], 1);
    g_csr[g_rowstart[d] + pos] = (src[e] << 2) | (attr[e] & 3);
}

__global__ void k_cat(const float* __restrict__ x, const float* __restrict__ ncc) {
    int i = blockIdx.x * blockDim.x + threadIdx.x;
    if (i >= NN * 40) return;
    int n = i / 40, k = i - n * 40;
    g_cat[i] = (k < 32) ? x[n * 32 + k] : ncc[n * 8 + (k - 32)];
}

// ---------------- TF32 tensor-core GEMM (3-pass split for fp32 accuracy) -----
// C[n,m] = sum_k A'[n,k] * W[m,k] + bias[m]
// where A'[n,k] = scl ? relu(A[n,k]*scl[k]+shf[k]) : A[n,k]   (fused BN+ReLU)
#define GBM 128
#define GBN 64
#define GBK 16
#define SAS 20   // smem row stride in floats (conflict-free for frag loads)

__device__ __forceinline__ unsigned f2tf32(float x) {
    unsigned r;
    asm("cvt.rna.tf32.f32 %0, %1;" : "=r"(r) : "f"(x));
    return r;
}

__device__ __forceinline__ void mma8(float* c, const unsigned* a, const unsigned* b) {
    asm volatile(
        "mma.sync.aligned.m16n8k8.row.col.f32.tf32.tf32.f32 "
        "{%0,%1,%2,%3}, {%4,%5,%6,%7}, {%8,%9}, {%0,%1,%2,%3};\n"
        : "+f"(c[0]), "+f"(c[1]), "+f"(c[2]), "+f"(c[3])
        : "r"(a[0]), "r"(a[1]), "r"(a[2]), "r"(a[3]), "r"(b[0]), "r"(b[1]));
}

__global__ __launch_bounds__(256) void k_gemm_tc(
    const float* __restrict__ A, const float* __restrict__ W,
    const float* __restrict__ bias,
    const float* __restrict__ scl, const float* __restrict__ shf,
    float* __restrict__ C, int nrows, int M, int K)
{
    __shared__ float As[GBM * SAS];
    __shared__ float Bs[GBN * SAS];
    int tid = threadIdx.x;
    int lane = tid & 31;
    int wid = tid >> 5;
    int gid = lane >> 2;      // 0..7
    int tig = lane & 3;       // 0..3
    int wm = wid & 3;         // 4 warps over M
    int wn = wid >> 2;        // 2 warps over N
    int row0 = blockIdx.y * GBM;
    int col0 = blockIdx.x * GBN;

    float acc[2][4][4];
    #pragma unroll
    for (int i = 0; i < 2; i++)
        #pragma unroll
        for (int j = 0; j < 4; j++)
            #pragma unroll
            for (int q = 0; q < 4; q++) acc[i][j][q] = 0.f;

    int ar = tid >> 1;          // 0..127 (A tile row)
    int ak = (tid & 1) * 8;     // 0 or 8
    int wr = tid >> 2;          // 0..63  (W tile row = C column)
    int wk = (tid & 3) * 4;     // 0,4,8,12

    for (int k0 = 0; k0 < K; k0 += GBK) {
        // --- A tile (with optional fused BN+ReLU transform) ---
        {
            int grow = row0 + ar;
            float4 v0 = {0.f, 0.f, 0.f, 0.f}, v1 = {0.f, 0.f, 0.f, 0.f};
            if (grow < nrows) {
                const float* ap = A + (size_t)grow * K + k0 + ak;
                if (k0 + ak + 4 <= K) {
                    v0 = *(const float4*)ap;
                    if (scl) {
                        int kb = k0 + ak;
                        v0.x = fmaxf(fmaf(v0.x, scl[kb + 0], shf[kb + 0]), 0.f);
                        v0.y = fmaxf(fmaf(v0.y, scl[kb + 1], shf[kb + 1]), 0.f);
                        v0.z = fmaxf(fmaf(v0.z, scl[kb + 2], shf[kb + 2]), 0.f);
                        v0.w = fmaxf(fmaf(v0.w, scl[kb + 3], shf[kb + 3]), 0.f);
                    }
                }
                if (k0 + ak + 8 <= K) {
                    v1 = *(const float4*)(ap + 4);
                    if (scl) {
                        int kb = k0 + ak + 4;
                        v1.x = fmaxf(fmaf(v1.x, scl[kb + 0], shf[kb + 0]), 0.f);
                        v1.y = fmaxf(fmaf(v1.y, scl[kb + 1], shf[kb + 1]), 0.f);
                        v1.z = fmaxf(fmaf(v1.z, scl[kb + 2], shf[kb + 2]), 0.f);
                        v1.w = fmaxf(fmaf(v1.w, scl[kb + 3], shf[kb + 3]), 0.f);
                    }
                }
            }
            *(float4*)&As[ar * SAS + ak] = v0;
            *(float4*)&As[ar * SAS + ak + 4] = v1;
        }
        // --- W tile ---
        {
            float4 w0 = {0.f, 0.f, 0.f, 0.f};
            if (k0 + wk + 4 <= K)
                w0 = *(const float4*)&W[(size_t)(col0 + wr) * K + k0 + wk];
            *(float4*)&Bs[wr * SAS + wk] = w0;
        }
        __syncthreads();

        #pragma unroll
        for (int ks = 0; ks < GBK; ks += 8) {
            unsigned ab[2][4], asm_[2][4];
            #pragma unroll
            for (int i = 0; i < 2; i++) {
                int rbase = wm * 32 + i * 16;
                #pragma unroll
                for (int q = 0; q < 4; q++) {
                    int rr = rbase + gid + (q & 1) * 8;
                    int kk = ks + tig + (q >> 1) * 4;
                    float x = As[rr * SAS + kk];
                    unsigned hb = f2tf32(x);
                    ab[i][q] = hb;
                    asm_[i][q] = f2tf32(x - __uint_as_float(hb));
                }
            }
            unsigned bb[4][2], bs_[4][2];
            #pragma unroll
            for (int j = 0; j < 4; j++) {
                int nn2 = wn * 32 + j * 8 + gid;
                #pragma unroll
                for (int q = 0; q < 2; q++) {
                    float x = Bs[nn2 * SAS + ks + tig + q * 4];
                    unsigned hb = f2tf32(x);
                    bb[j][q] = hb;
                    bs_[j][q] = f2tf32(x - __uint_as_float(hb));
                }
            }
            #pragma unroll
            for (int i = 0; i < 2; i++)
                #pragma unroll
                for (int j = 0; j < 4; j++) {
                    mma8(acc[i][j], ab[i], bb[j]);
                    mma8(acc[i][j], ab[i], bs_[j]);
                    mma8(acc[i][j], asm_[i], bb[j]);
                }
        }
        __syncthreads();
    }

    // --- epilogue: bias + store ---
    #pragma unroll
    for (int i = 0; i < 2; i++) {
        int r1 = row0 + wm * 32 + i * 16 + gid;
        #pragma unroll
        for (int j = 0; j < 4; j++) {
            int c = col0 + wn * 32 + j * 8 + tig * 2;
            float2 b2 = *(const float2*)&bias[c];
            if (r1 < nrows) {
                float2 o = {acc[i][j][0] + b2.x, acc[i][j][1] + b2.y};
                *(float2*)&C[(size_t)r1 * M + c] = o;
            }
            if (r1 + 8 < nrows) {
                float2 o = {acc[i][j][2] + b2.x, acc[i][j][3] + b2.y};
                *(float2*)&C[(size_t)(r1 + 8) * M + c] = o;
            }
        }
    }
}

// ---------------- column stats (sum, sumsq) over nrows ------------------------
__global__ void k_colstats(const float* __restrict__ C, int M) {
    int m = threadIdx.x;                  // blockDim.x == M
    float s = 0.f, q = 0.f;
    for (int r = blockIdx.x; r < NN; r += gridDim.x) {
        float v = C[(size_t)r * M + m];
        s += v; q += v * v;
    }
    atomicAdd(&g_cstat[m], s);
    atomicAdd(&g_cstat[512 + m], q);
}

// precompute BN scale/shift: scale = rsqrt(var+eps)*gamma, shift = beta - mu*scale
__global__ void k_bnprep(const float* __restrict__ gam, const float* __restrict__ bet,
                         int M) {
    int m = blockIdx.x * blockDim.x + threadIdx.x;
    if (m >= M) return;
    float invN = 1.f / (float)NN;
    float mu = g_cstat[m] * invN;
    float var = g_cstat[512 + m] * invN - mu * mu;
    float sc = rsqrtf(var + 1e-5f) * gam[m];
    g_ss[m] = sc;
    g_ss[512 + m] = bet[m] - mu * sc;
}

__global__ void k_bnrelu(const float* __restrict__ X, float* __restrict__ Y,
                         const float* __restrict__ gam, const float* __restrict__ bet,
                         int M) {
    int i = blockIdx.x * blockDim.x + threadIdx.x;
    if (i >= NN * M) return;
    int m = i % M;
    float invN = 1.f / (float)NN;
    float mu = g_cstat[m] * invN;
    float var = g_cstat[512 + m] * invN - mu * mu;
    float v = (X[i] - mu) * rsqrtf(var + 1e-5f) * gam[m] + bet[m];
    Y[i] = v > 0.f ? v : 0.f;
}

// ---------------- fused edge aggregation: warp per node, online softmax -------
__global__ void k_agg(const float* __restrict__ h, const float* __restrict__ eemb,
                      float* __restrict__ out) {
    int warp = (blockIdx.x * blockDim.x + threadIdx.x) >> 5;
    int lane = threadIdx.x & 31;
    if (warp >= NN) return;
    int n = warp;
    int beg = g_rowstart[n], end = g_rowstart[n + 1];
    float m[4] = {-1e30f, -1e30f, -1e30f, -1e30f};
    float s[4] = {0.f, 0.f, 0.f, 0.f};
    float w[4] = {0.f, 0.f, 0.f, 0.f};
    int co = lane * 4;
    for (int j = beg; j < end; j++) {
        int p = __ldg(&g_csr[j]);
        int src = p >> 2;
        int a = p & 3;
        float4 hv = *(const float4*)&h[(size_t)src * HH + co];
        float4 ev = *(const float4*)&eemb[a * HH + co];
        float msg[4];
        msg[0] = fmaxf(hv.x + ev.x, 0.f) + EPS_GEN;
        msg[1] = fmaxf(hv.y + ev.y, 0.f) + EPS_GEN;
        msg[2] = fmaxf(hv.z + ev.z, 0.f) + EPS_GEN;
        msg[3] = fmaxf(hv.w + ev.w, 0.f) + EPS_GEN;
        #pragma unroll
        for (int c = 0; c < 4; c++) {
            if (msg[c] > m[c]) {
                float sc = __expf(m[c] - msg[c]);
                s[c] *= sc; w[c] *= sc; m[c] = msg[c];
            }
            float e = __expf(msg[c] - m[c]);
            s[c] += e;
            w[c] += e * msg[c];
        }
    }
    float4 hn = *(const float4*)&h[(size_t)n * HH + co];
    bool has = end > beg;
    float4 o;
    o.x = (has ? w[0] / s[0] : 0.f) + hn.x;
    o.y = (has ? w[1] / s[1] : 0.f) + hn.y;
    o.z = (has ? w[2] / s[2] : 0.f) + hn.z;
    o.w = (has ? w[3] / s[3] : 0.f) + hn.w;
    *(float4*)&out[(size_t)n * HH + co] = o;
}

// ---------------- pooling ------------------------------------------------------
__global__ void k_pool(const float* __restrict__ h, const int* __restrict__ batch) {
    int i = blockIdx.x * blockDim.x + threadIdx.x;
    if (i >= NN * 32) return;
    int n = i >> 5;
    int lane = i & 31;
    int g = batch[n];
    float4 v = *(const float4*)&h[(size_t)n * HH + lane * 4];
    float* dst = &g_p[(size_t)g * HH + lane * 4];
    atomicAdd(dst + 0, v.x);
    atomicAdd(dst + 1, v.y);
    atomicAdd(dst + 2, v.z);
    atomicAdd(dst + 3, v.w);
}

// ---------------- head: LSTM (1 step, h0=c0=0) + final linear ------------------
__device__ __forceinline__ float sigm(float x) { return 1.f / (1.f + __expf(-x)); }

__global__ void k_head(const float* __restrict__ wih, const float* __restrict__ bih,
                       const float* __restrict__ bhh, const float* __restrict__ linw,
                       const float* __restrict__ linb, float* __restrict__ out) {
    __shared__ float ps[HH];
    __shared__ float gs[4 * LH];
    __shared__ float hh[LH];
    int g = blockIdx.x;
    int t = threadIdx.x;       // 256 threads
    if (t < HH) ps[t] = g_p[(size_t)g * HH + t];
    __syncthreads();
    {
        float acc = bih[t] + bhh[t];
        const float* wr = &wih[(size_t)t * HH];
        #pragma unroll 8
        for (int k = 0; k < HH; k++) acc = fmaf(ps[k], wr[k], acc);
        gs[t] = acc;
    }
    __syncthreads();
    if (t < LH) {
        float ig = gs[t];
        float gg = gs[t + 2 * LH];
        float og = gs[t + 3 * LH];
        float c = sigm(ig) * tanhf(gg);
        hh[t] = sigm(og) * tanhf(c);
    }
    __syncthreads();
    if (t < OUTC) {
        float acc = linb[t];
        const float* wr = &linw[(size_t)t * LH];
        #pragma unroll
        for (int k = 0; k < LH; k++) acc = fmaf(hh[k], wr[k], acc);
        out[(size_t)g * OUTC + t] = acc;
    }
}

// ---------------- launch -------------------------------------------------------
extern "C" void kernel_launch(void* const* d_in, const int* in_sizes, int n_in,
                              void* d_out, int out_size) {
    const float* x        = (const float*)d_in[0];
    const float* ncc      = (const float*)d_in[1];
    const int*   eidx     = (const int*)d_in[2];
    const int*   eattr    = (const int*)d_in[3];
    const int*   batch    = (const int*)d_in[4];
    const float* fc_w     = (const float*)d_in[5];
    const float* fc_b     = (const float*)d_in[6];
    const float* edge_emb = (const float*)d_in[7];
    const float* conv_w1  = (const float*)d_in[8];
    const float* conv_b1  = (const float*)d_in[9];
    const float* cbn_g    = (const float*)d_in[10];
    const float* cbn_b    = (const float*)d_in[11];
    const float* conv_w2  = (const float*)d_in[12];
    const float* conv_b2  = (const float*)d_in[13];
    const float* bn_g     = (const float*)d_in[14];
    const float* bn_b     = (const float*)d_in[15];
    const float* lstm_wih = (const float*)d_in[16];
    const float* lstm_whh = (const float*)d_in[17];  // unused (h0 = 0)
    const float* lstm_bih = (const float*)d_in[18];
    const float* lstm_bhh = (const float*)d_in[19];
    const float* lin_w    = (const float*)d_in[20];
    const float* lin_b    = (const float*)d_in[21];
    (void)lstm_whh; (void)n_in; (void)in_sizes; (void)out_size;
    float* outp = (float*)d_out;

    const int* src = eidx;
    const int* dst = eidx + EE;

    int *p_deg, *p_cursor;
    float *p_h, *p_xin, *p_hmid, *p_hraw, *p_cat, *p_cstat, *p_ss, *p_pool;
    cudaGetSymbolAddress((void**)&p_deg, g_deg);
    cudaGetSymbolAddress((void**)&p_cursor, g_cursor);
    cudaGetSymbolAddress((void**)&p_h, g_h);
    cudaGetSymbolAddress((void**)&p_xin, g_xin);
    cudaGetSymbolAddress((void**)&p_hmid, g_hmid);
    cudaGetSymbolAddress((void**)&p_hraw, g_hraw);
    cudaGetSymbolAddress((void**)&p_cat, g_cat);
    cudaGetSymbolAddress((void**)&p_cstat, g_cstat);
    cudaGetSymbolAddress((void**)&p_ss, g_ss);
    cudaGetSymbolAddress((void**)&p_pool, g_p);

    // --- CSR build ---
    k_zero2_int<<<(NN + 255) / 256, 256>>>(p_deg, p_cursor, NN);
    k_hist<<<(EE + 255) / 256, 256>>>(dst);
    k_scan<<<1, 1024>>>();
    k_scatter<<<(EE + 255) / 256, 256>>>(src, dst, eattr);

    // --- initial FC: h = concat(x,ncc) @ fc_w^T + fc_b ---
    k_cat<<<(NN * 40 + 255) / 256, 256>>>(x, ncc);
    {
        dim3 grid(HH / GBN, (NN + GBM - 1) / GBM);
        k_gemm_tc<<<grid, 256>>>(p_cat, fc_w, fc_b, nullptr, nullptr, p_h, NN, HH, 40);
    }

    // --- layers ---
    for (int l = 0; l < LL; l++) {
        // edge aggregation + residual -> xin
        k_agg<<<(NN * 32 + 255) / 256, 256>>>(p_h, edge_emb, p_xin);

        // GEMM1: [N,128] x [256,128]^T -> [N,256]  (raw pre-BN output)
        {
            dim3 grid((2 * HH) / GBN, (NN + GBM - 1) / GBM);
            k_gemm_tc<<<grid, 256>>>(p_xin, conv_w1 + (size_t)l * 2 * HH * HH,
                                     conv_b1 + (size_t)l * 2 * HH,
                                     nullptr, nullptr, p_hmid, NN, 2 * HH, HH);
        }
        k_zero_f<<<4, 256>>>(p_cstat, 1024);
        k_colstats<<<256, 2 * HH>>>(p_hmid, 2 * HH);
        k_bnprep<<<1, 256>>>(cbn_g + (size_t)l * 2 * HH, cbn_b + (size_t)l * 2 * HH, 2 * HH);

        // GEMM2: [N,256] x [128,256]^T -> [N,128]  (BN+ReLU fused into A load)
        {
            dim3 grid(HH / GBN, (NN + GBM - 1) / GBM);
            k_gemm_tc<<<grid, 256>>>(p_hmid, conv_w2 + (size_t)l * HH * 2 * HH,
                                     conv_b2 + (size_t)l * HH,
                                     p_ss, p_ss + 512, p_hraw, NN, HH, 2 * HH);
        }
        k_zero_f<<<4, 256>>>(p_cstat, 1024);
        k_colstats<<<256, HH>>>(p_hraw, HH);
        k_bnrelu<<<(NN * HH + 255) / 256, 256>>>(p_hraw, p_h,
                                                 bn_g + (size_t)l * HH,
                                                 bn_b + (size_t)l * HH, HH);
    }

    // --- pool + head ---
    k_zero_f<<<(GG * HH + 255) / 256, 256>>>(p_pool, GG * HH);
    k_pool<<<(NN * 32 + 255) / 256, 256>>>(p_h, batch);
    k_head<<<GG, 256>>>(lstm_wih, lstm_bih, lstm_bhh, lin_w, lin_b, outp);
}

// round 3
// speedup vs baseline: 1.7970x; 1.4903x over previous
#include <cuda_runtime.h>
#include <cuda_bf16.h>
#include <math.h>
#include <stdint.h>

#define NN 50000
#define EE 640000
#define GG 256
#define INC 32
#define HH 128
#define LL 5
#define LH 64
#define OUTC 10
#define EPS_GEN 1e-7f

// ---------------- scratch (static device globals; no runtime alloc) ----------
__device__ float g_h[NN * HH];        // FC output (layer-0 input)
__device__ float g_xin[NN * HH];      // agg + h (GEMM1 input)
__device__ float g_hmid[NN * 2 * HH]; // GEMM1 out (raw, pre-BN)
__device__ float g_hraw[NN * HH];     // GEMM2 out (raw, pre-BN)
__device__ float g_cat[NN * 40];      // concat(x, ncc)
__device__ int   g_deg[NN];
__device__ int   g_cursor[NN];
__device__ int   g_rowstart[NN + 1];
__device__ int   g_csr[EE];           // packed (src<<2)|attr
__device__ float g_st1[512];          // stage1 stats: sum[0:256], sumsq[256:512]
__device__ float g_st2[256];          // stage2 stats: sum[0:128], sumsq[128:256]
__device__ float g_ss1[512];          // stage1 BN scale[0:256], shift[256:512]
__device__ float g_ss2[256];          // stage2 BN scale[0:128], shift[128:256]
__device__ float g_p[GG * HH];        // pooled

// ---------------- utility kernels -------------------------------------------
__global__ void k_zero2_int(int* a, int* b, int n) {
    int i = blockIdx.x * blockDim.x + threadIdx.x;
    if (i < n) { a[i] = 0; b[i] = 0; }
}
__global__ void k_zero_f(float* a, int n) {
    int i = blockIdx.x * blockDim.x + threadIdx.x;
    if (i < n) a[i] = 0.f;
}
__global__ void k_zero_st(float* a, float* b) {
    int i = blockIdx.x * blockDim.x + threadIdx.x;
    if (i < 512) a[i] = 0.f;
    if (i < 256) b[i] = 0.f;
}

__global__ void k_hist(const int* __restrict__ dst) {
    int e = blockIdx.x * blockDim.x + threadIdx.x;
    if (e < EE) atomicAdd(&g_deg[dst[e]], 1);
}

// single-block exclusive scan of g_deg -> g_rowstart (N+1 entries)
__global__ void k_scan() {
    __shared__ int sh[1024];
    int t = threadIdx.x;
    int running = 0;
    for (int base = 0; base < NN; base += 1024) {
        int v = (base + t < NN) ? g_deg[base + t] : 0;
        sh[t] = v;
        __syncthreads();
        #pragma unroll
        for (int off = 1; off < 1024; off <<= 1) {
            int u = (t >= off) ? sh[t - off] : 0;
            __syncthreads();
            sh[t] += u;
            __syncthreads();
        }
        int incl = sh[t];
        if (base + t < NN) g_rowstart[base + t] = running + incl - v;
        int tot = sh[1023];
        __syncthreads();
        running += tot;
    }
    if (t == 0) g_rowstart[NN] = running;
}

__global__ void k_scatter(const int* __restrict__ src, const int* __restrict__ dst,
                          const int* __restrict__ attr) {
    int e = blockIdx.x * blockDim.x + threadIdx.x;
    if (e >= EE) return;
    int d = dst[e];
    int pos = atomicAdd(&g_cursor[d], 1);
    g_csr[g_rowstart[d] + pos] = (src[e] << 2) | (attr[e] & 3);
}

__global__ void k_cat(const float* __restrict__ x, const float* __restrict__ ncc) {
    int i = blockIdx.x * blockDim.x + threadIdx.x;
    if (i >= NN * 40) return;
    int n = i / 40, k = i - n * 40;
    g_cat[i] = (k < 32) ? x[n * 32 + k] : ncc[n * 8 + (k - 32)];
}

// ================= bf16 split-2 tensor-core GEMM ==============================
// C[n,m] = sum_k A'[n,k] * W[m,k] + bias[m]
//   A'[n,k] = scl ? relu(A[n,k]*scl[k]+shf[k]) : A[n,k]   (fused BN+ReLU on input)
// optional stats: colsum -> stats[0:M), colsumsq -> stats[M:2M) (atomic)
#define GBM 128
#define GBN 64
#define GBK 32
#define ASTR 40   // smem row stride in bf16 elems (80B: ldmatrix conflict-free)

__device__ __forceinline__ void mma16(float* c, const uint32_t* a, const uint32_t* b) {
    asm volatile(
        "mma.sync.aligned.m16n8k16.row.col.f32.bf16.bf16.f32 "
        "{%0,%1,%2,%3}, {%4,%5,%6,%7}, {%8,%9}, {%0,%1,%2,%3};\n"
        : "+f"(c[0]), "+f"(c[1]), "+f"(c[2]), "+f"(c[3])
        : "r"(a[0]), "r"(a[1]), "r"(a[2]), "r"(a[3]), "r"(b[0]), "r"(b[1]));
}

__device__ __forceinline__ void split_pair(float x0, float x1,
                                           uint32_t& hi, uint32_t& lo) {
    __nv_bfloat16 h0 = __float2bfloat16(x0), h1 = __float2bfloat16(x1);
    float r0 = x0 - __bfloat162float(h0);
    float r1 = x1 - __bfloat162float(h1);
    __nv_bfloat16 l0 = __float2bfloat16(r0), l1 = __float2bfloat16(r1);
    hi = (uint32_t)*(uint16_t*)&h0 | ((uint32_t)*(uint16_t*)&h1 << 16);
    lo = (uint32_t)*(uint16_t*)&l0 | ((uint32_t)*(uint16_t*)&l1 << 16);
}

__global__ __launch_bounds__(256) void k_gemm_bf16(
    const float* __restrict__ A, const float* __restrict__ W,
    const float* __restrict__ bias,
    const float* __restrict__ scl, const float* __restrict__ shf,
    float* __restrict__ C, float* __restrict__ stats,
    int nrows, int M, int K)
{
    __shared__ __align__(16) uint16_t As[2][GBM * ASTR];
    __shared__ __align__(16) uint16_t Bs[2][GBN * ASTR];

    int tid = threadIdx.x, lane = tid & 31, wid = tid >> 5;
    int gid = lane >> 2, tig = lane & 3;
    int wm = wid & 3, wn = wid >> 2;
    int row0 = blockIdx.y * GBM, col0 = blockIdx.x * GBN;

    float acc[2][4][4];
    #pragma unroll
    for (int i = 0; i < 2; i++)
        #pragma unroll
        for (int j = 0; j < 4; j++)
            #pragma unroll
            for (int q = 0; q < 4; q++) acc[i][j][q] = 0.f;

    // staging indices
    int s_ar = tid >> 1;            // A tile row 0..127
    int s_ak = (tid & 1) * 16;      // 0 / 16
    int s_wr = tid >> 2;            // W tile row 0..63
    int s_wk = (tid & 3) * 8;       // 0,8,16,24

    // ldmatrix per-lane offsets
    int l7 = lane & 7, l8 = (lane >> 3) & 1, l16 = lane >> 4;
    uint32_t as_base[2] = { (uint32_t)__cvta_generic_to_shared(&As[0][0]),
                            (uint32_t)__cvta_generic_to_shared(&As[1][0]) };
    uint32_t bs_base[2] = { (uint32_t)__cvta_generic_to_shared(&Bs[0][0]),
                            (uint32_t)__cvta_generic_to_shared(&Bs[1][0]) };
    uint32_t aoff[2], boff[2];
    #pragma unroll
    for (int i = 0; i < 2; i++)
        aoff[i] = ((wm * 32 + i * 16 + l7 + l8 * 8) * ASTR + l16 * 8) * 2;
    #pragma unroll
    for (int jp = 0; jp < 2; jp++)
        boff[jp] = ((wn * 32 + jp * 16 + l7 + l16 * 8) * ASTR + l8 * 8) * 2;

    for (int k0 = 0; k0 < K; k0 += GBK) {
        // ---- stage A tile (fp32 -> bf16 hi/lo planes, optional fused BN+ReLU) ----
        {
            int grow = row0 + s_ar;
            bool rok = grow < nrows;
            float v[16];
            #pragma unroll
            for (int f = 0; f < 4; f++) {
                int kg = k0 + s_ak + f * 4;
                float4 t = make_float4(0.f, 0.f, 0.f, 0.f);
                if (rok && kg + 4 <= K) {
                    t = *(const float4*)&A[(size_t)grow * K + kg];
                    if (scl) {
                        t.x = fmaxf(fmaf(t.x, scl[kg + 0], shf[kg + 0]), 0.f);
                        t.y = fmaxf(fmaf(t.y, scl[kg + 1], shf[kg + 1]), 0.f);
                        t.z = fmaxf(fmaf(t.z, scl[kg + 2], shf[kg + 2]), 0.f);
                        t.w = fmaxf(fmaf(t.w, scl[kg + 3], shf[kg + 3]), 0.f);
                    }
                }
                v[f * 4 + 0] = t.x; v[f * 4 + 1] = t.y;
                v[f * 4 + 2] = t.z; v[f * 4 + 3] = t.w;
            }
            uint32_t hi[8], lo[8];
            #pragma unroll
            for (int e = 0; e < 8; e++) split_pair(v[2 * e], v[2 * e + 1], hi[e], lo[e]);
            uint32_t off = s_ar * ASTR + s_ak;
            *(uint4*)&As[0][off]     = make_uint4(hi[0], hi[1], hi[2], hi[3]);
            *(uint4*)&As[0][off + 8] = make_uint4(hi[4], hi[5], hi[6], hi[7]);
            *(uint4*)&As[1][off]     = make_uint4(lo[0], lo[1], lo[2], lo[3]);
            *(uint4*)&As[1][off + 8] = make_uint4(lo[4], lo[5], lo[6], lo[7]);
        }
        // ---- stage B tile ----
        {
            int wrow = col0 + s_wr;   // always < M (M multiple of 64)
            float v[8];
            #pragma unroll
            for (int f = 0; f < 2; f++) {
                int kg = k0 + s_wk + f * 4;
                float4 t = make_float4(0.f, 0.f, 0.f, 0.f);
                if (kg + 4 <= K) t = *(const float4*)&W[(size_t)wrow * K + kg];
                v[f * 4 + 0] = t.x; v[f * 4 + 1] = t.y;
                v[f * 4 + 2] = t.z; v[f * 4 + 3] = t.w;
            }
            uint32_t hi[4], lo[4];
            #pragma unroll
            for (int e = 0; e < 4; e++) split_pair(v[2 * e], v[2 * e + 1], hi[e], lo[e]);
            uint32_t off = s_wr * ASTR + s_wk;
            *(uint4*)&Bs[0][off] = make_uint4(hi[0], hi[1], hi[2], hi[3]);
            *(uint4*)&Bs[1][off] = make_uint4(lo[0], lo[1], lo[2], lo[3]);
        }
        __syncthreads();

        #pragma unroll
        for (int ksx = 0; ksx < 2; ksx++) {
            uint32_t ksb = ksx * 32;   // 16 bf16 = 32 bytes
            uint32_t a[2][2][4];       // [plane][i][reg]
            uint32_t b[2][4][2];       // [plane][j][reg]
            #pragma unroll
            for (int p = 0; p < 2; p++)
                #pragma unroll
                for (int i = 0; i < 2; i++) {
                    uint32_t ad = as_base[p] + aoff[i] + ksb;
                    asm volatile(
                        "ldmatrix.sync.aligned.m8n8.x4.shared.b16 {%0,%1,%2,%3}, [%4];"
                        : "=r"(a[p][i][0]), "=r"(a[p][i][1]),
                          "=r"(a[p][i][2]), "=r"(a[p][i][3])
                        : "r"(ad));
                }
            #pragma unroll
            for (int p = 0; p < 2; p++)
                #pragma unroll
                for (int jp = 0; jp < 2; jp++) {
                    uint32_t ad = bs_base[p] + boff[jp] + ksb;
                    asm volatile(
                        "ldmatrix.sync.aligned.m8n8.x4.shared.b16 {%0,%1,%2,%3}, [%4];"
                        : "=r"(b[p][jp * 2][0]), "=r"(b[p][jp * 2][1]),
                          "=r"(b[p][jp * 2 + 1][0]), "=r"(b[p][jp * 2 + 1][1])
                        : "r"(ad));
                }
            #pragma unroll
            for (int i = 0; i < 2; i++)
                #pragma unroll
                for (int j = 0; j < 4; j++) {
                    mma16(acc[i][j], a[0][i], b[0][j]);   // hi*hi
                    mma16(acc[i][j], a[0][i], b[1][j]);   // hi*lo
                    mma16(acc[i][j], a[1][i], b[0][j]);   // lo*hi
                }
        }
        __syncthreads();
    }

    // ---- epilogue: bias, store, optional column stats ----
    #pragma unroll
    for (int i = 0; i < 2; i++)
        #pragma unroll
        for (int j = 0; j < 4; j++) {
            int c = col0 + wn * 32 + j * 8 + tig * 2;
            float2 b2 = *(const float2*)&bias[c];
            acc[i][j][0] += b2.x; acc[i][j][1] += b2.y;
            acc[i][j][2] += b2.x; acc[i][j][3] += b2.y;
        }
    #pragma unroll
    for (int i = 0; i < 2; i++) {
        int r = row0 + wm * 32 + i * 16 + gid;
        #pragma unroll
        for (int j = 0; j < 4; j++) {
            int c = col0 + wn * 32 + j * 8 + tig * 2;
            if (r < nrows) {
                float2 o = {acc[i][j][0], acc[i][j][1]};
                *(float2*)&C[(size_t)r * M + c] = o;
            }
            if (r + 8 < nrows) {
                float2 o = {acc[i][j][2], acc[i][j][3]};
                *(float2*)&C[(size_t)(r + 8) * M + c] = o;
            }
        }
    }
    if (stats) {
        #pragma unroll
        for (int j = 0; j < 4; j++)
            #pragma unroll
            for (int qc = 0; qc < 2; qc++) {
                float sv = 0.f, qv = 0.f;
                #pragma unroll
                for (int i = 0; i < 2; i++) {
                    int r = row0 + wm * 32 + i * 16 + gid;
                    if (r < nrows)     { float v = acc[i][j][qc];     sv += v; qv += v * v; }
                    if (r + 8 < nrows) { float v = acc[i][j][qc + 2]; sv += v; qv += v * v; }
                }
                #pragma unroll
                for (int o = 4; o < 32; o <<= 1) {
                    sv += __shfl_xor_sync(0xffffffffu, sv, o);
                    qv += __shfl_xor_sync(0xffffffffu, qv, o);
                }
                if (lane < 4) {
                    int c = col0 + wn * 32 + j * 8 + tig * 2 + qc;
                    atomicAdd(&stats[c], sv);
                    atomicAdd(&stats[M + c], qv);
                }
            }
    }
}

// precompute BN scale/shift from stats: scale = rsqrt(var+eps)*gamma, shift = beta - mu*scale
__global__ void k_bnprep(const float* __restrict__ stats,
                         const float* __restrict__ gam, const float* __restrict__ bet,
                         float* __restrict__ ss, int M) {
    int m = blockIdx.x * blockDim.x + threadIdx.x;
    if (m >= M) return;
    float invN = 1.f / (float)NN;
    float mu = stats[m] * invN;
    float var = stats[M + m] * invN - mu * mu;
    float sc = rsqrtf(var + 1e-5f) * gam[m];
    ss[m] = sc;
    ss[M + m] = bet[m] - mu * sc;
}

// ---------------- fused edge aggregation (+ BN/ReLU of input on the fly) ------
__global__ void k_agg(const float* __restrict__ h, const float* __restrict__ eemb,
                      const float* __restrict__ scl, const float* __restrict__ shf,
                      float* __restrict__ out) {
    int warp = (blockIdx.x * blockDim.x + threadIdx.x) >> 5;
    int lane = threadIdx.x & 31;
    if (warp >= NN) return;
    int n = warp;
    int beg = g_rowstart[n], end = g_rowstart[n + 1];
    int co = lane * 4;
    bool bn = (scl != nullptr);
    float4 sc = make_float4(1.f, 1.f, 1.f, 1.f), sh = make_float4(0.f, 0.f, 0.f, 0.f);
    if (bn) { sc = *(const float4*)&scl[co]; sh = *(const float4*)&shf[co]; }
    float m[4] = {-1e30f, -1e30f, -1e30f, -1e30f};
    float s[4] = {0.f, 0.f, 0.f, 0.f};
    float w[4] = {0.f, 0.f, 0.f, 0.f};
    for (int j = beg; j < end; j++) {
        int p = __ldg(&g_csr[j]);
        int src = p >> 2;
        int a = p & 3;
        float4 hv = *(const float4*)&h[(size_t)src * HH + co];
        if (bn) {
            hv.x = fmaxf(fmaf(hv.x, sc.x, sh.x), 0.f);
            hv.y = fmaxf(fmaf(hv.y, sc.y, sh.y), 0.f);
            hv.z = fmaxf(fmaf(hv.z, sc.z, sh.z), 0.f);
            hv.w = fmaxf(fmaf(hv.w, sc.w, sh.w), 0.f);
        }
        float4 ev = *(const float4*)&eemb[a * HH + co];
        float msg[4];
        msg[0] = fmaxf(hv.x + ev.x, 0.f) + EPS_GEN;
        msg[1] = fmaxf(hv.y + ev.y, 0.f) + EPS_GEN;
        msg[2] = fmaxf(hv.z + ev.z, 0.f) + EPS_GEN;
        msg[3] = fmaxf(hv.w + ev.w, 0.f) + EPS_GEN;
        #pragma unroll
        for (int c = 0; c < 4; c++) {
            if (msg[c] > m[c]) {
                float f = __expf(m[c] - msg[c]);
                s[c] *= f; w[c] *= f; m[c] = msg[c];
            }
            float e = __expf(msg[c] - m[c]);
            s[c] += e;
            w[c] += e * msg[c];
        }
    }
    float4 hn = *(const float4*)&h[(size_t)n * HH + co];
    if (bn) {
        hn.x = fmaxf(fmaf(hn.x, sc.x, sh.x), 0.f);
        hn.y = fmaxf(fmaf(hn.y, sc.y, sh.y), 0.f);
        hn.z = fmaxf(fmaf(hn.z, sc.z, sh.z), 0.f);
        hn.w = fmaxf(fmaf(hn.w, sc.w, sh.w), 0.f);
    }
    bool has = end > beg;
    float4 o;
    o.x = (has ? w[0] / s[0] : 0.f) + hn.x;
    o.y = (has ? w[1] / s[1] : 0.f) + hn.y;
    o.z = (has ? w[2] / s[2] : 0.f) + hn.z;
    o.w = (has ? w[3] / s[3] : 0.f) + hn.w;
    *(float4*)&out[(size_t)n * HH + co] = o;
}

// ---------------- pooling (applies final-layer BN+ReLU on the fly) ------------
__global__ void k_pool(const float* __restrict__ h, const int* __restrict__ batch,
                       const float* __restrict__ scl, const float* __restrict__ shf) {
    int i = blockIdx.x * blockDim.x + threadIdx.x;
    if (i >= NN * 32) return;
    int n = i >> 5;
    int lane = i & 31;
    int co = lane * 4;
    int g = batch[n];
    float4 v = *(const float4*)&h[(size_t)n * HH + co];
    float4 sc = *(const float4*)&scl[co];
    float4 sh = *(const float4*)&shf[co];
    v.x = fmaxf(fmaf(v.x, sc.x, sh.x), 0.f);
    v.y = fmaxf(fmaf(v.y, sc.y, sh.y), 0.f);
    v.z = fmaxf(fmaf(v.z, sc.z, sh.z), 0.f);
    v.w = fmaxf(fmaf(v.w, sc.w, sh.w), 0.f);
    float* dst = &g_p[(size_t)g * HH + co];
    atomicAdd(dst + 0, v.x);
    atomicAdd(dst + 1, v.y);
    atomicAdd(dst + 2, v.z);
    atomicAdd(dst + 3, v.w);
}

// ---------------- head: LSTM (1 step, h0=c0=0) + final linear ------------------
__device__ __forceinline__ float sigm(float x) { return 1.f / (1.f + __expf(-x)); }

__global__ void k_head(const float* __restrict__ wih, const float* __restrict__ bih,
                       const float* __restrict__ bhh, const float* __restrict__ linw,
                       const float* __restrict__ linb, float* __restrict__ out) {
    __shared__ float ps[HH];
    __shared__ float gs[4 * LH];
    __shared__ float hh[LH];
    int g = blockIdx.x;
    int t = threadIdx.x;       // 256 threads
    if (t < HH) ps[t] = g_p[(size_t)g * HH + t];
    __syncthreads();
    {
        float acc = bih[t] + bhh[t];
        const float* wr = &wih[(size_t)t * HH];
        #pragma unroll 8
        for (int k = 0; k < HH; k++) acc = fmaf(ps[k], wr[k], acc);
        gs[t] = acc;
    }
    __syncthreads();
    if (t < LH) {
        float ig = gs[t];
        float gg = gs[t + 2 * LH];
        float og = gs[t + 3 * LH];
        float c = sigm(ig) * tanhf(gg);
        hh[t] = sigm(og) * tanhf(c);
    }
    __syncthreads();
    if (t < OUTC) {
        float acc = linb[t];
        const float* wr = &linw[(size_t)t * LH];
        #pragma unroll
        for (int k = 0; k < LH; k++) acc = fmaf(hh[k], wr[k], acc);
        out[(size_t)g * OUTC + t] = acc;
    }
}

// ---------------- launch -------------------------------------------------------
extern "C" void kernel_launch(void* const* d_in, const int* in_sizes, int n_in,
                              void* d_out, int out_size) {
    const float* x        = (const float*)d_in[0];
    const float* ncc      = (const float*)d_in[1];
    const int*   eidx     = (const int*)d_in[2];
    const int*   eattr    = (const int*)d_in[3];
    const int*   batch    = (const int*)d_in[4];
    const float* fc_w     = (const float*)d_in[5];
    const float* fc_b     = (const float*)d_in[6];
    const float* edge_emb = (const float*)d_in[7];
    const float* conv_w1  = (const float*)d_in[8];
    const float* conv_b1  = (const float*)d_in[9];
    const float* cbn_g    = (const float*)d_in[10];
    const float* cbn_b    = (const float*)d_in[11];
    const float* conv_w2  = (const float*)d_in[12];
    const float* conv_b2  = (const float*)d_in[13];
    const float* bn_g     = (const float*)d_in[14];
    const float* bn_b     = (const float*)d_in[15];
    const float* lstm_wih = (const float*)d_in[16];
    const float* lstm_whh = (const float*)d_in[17];  // unused (h0 = 0)
    const float* lstm_bih = (const float*)d_in[18];
    const float* lstm_bhh = (const float*)d_in[19];
    const float* lin_w    = (const float*)d_in[20];
    const float* lin_b    = (const float*)d_in[21];
    (void)lstm_whh; (void)n_in; (void)in_sizes; (void)out_size;
    float* outp = (float*)d_out;

    const int* src = eidx;
    const int* dst = eidx + EE;

    int *p_deg, *p_cursor;
    float *p_h, *p_xin, *p_hmid, *p_hraw, *p_cat, *p_st1, *p_st2, *p_ss1, *p_ss2, *p_pool;
    cudaGetSymbolAddress((void**)&p_deg, g_deg);
    cudaGetSymbolAddress((void**)&p_cursor, g_cursor);
    cudaGetSymbolAddress((void**)&p_h, g_h);
    cudaGetSymbolAddress((void**)&p_xin, g_xin);
    cudaGetSymbolAddress((void**)&p_hmid, g_hmid);
    cudaGetSymbolAddress((void**)&p_hraw, g_hraw);
    cudaGetSymbolAddress((void**)&p_cat, g_cat);
    cudaGetSymbolAddress((void**)&p_st1, g_st1);
    cudaGetSymbolAddress((void**)&p_st2, g_st2);
    cudaGetSymbolAddress((void**)&p_ss1, g_ss1);
    cudaGetSymbolAddress((void**)&p_ss2, g_ss2);
    cudaGetSymbolAddress((void**)&p_pool, g_p);

    // --- CSR build ---
    k_zero2_int<<<(NN + 255) / 256, 256>>>(p_deg, p_cursor, NN);
    k_hist<<<(EE + 255) / 256, 256>>>(dst);
    k_scan<<<1, 1024>>>();
    k_scatter<<<(EE + 255) / 256, 256>>>(src, dst, eattr);

    // --- initial FC: h = concat(x,ncc) @ fc_w^T + fc_b ---
    k_cat<<<(NN * 40 + 255) / 256, 256>>>(x, ncc);
    {
        dim3 grid(HH / GBN, (NN + GBM - 1) / GBM);
        k_gemm_bf16<<<grid, 256>>>(p_cat, fc_w, fc_b, nullptr, nullptr,
                                   p_h, nullptr, NN, HH, 40);
    }

    // --- layers ---
    for (int l = 0; l < LL; l++) {
        // edge aggregation (+ BN/ReLU of previous layer output) -> xin
        const float* hin = (l == 0) ? p_h : p_hraw;
        const float* asc = (l == 0) ? nullptr : p_ss2;
        const float* ash = (l == 0) ? nullptr : p_ss2 + HH;
        k_agg<<<(NN * 32 + 255) / 256, 256>>>(hin, edge_emb, asc, ash, p_xin);

        k_zero_st<<<2, 256>>>(p_st1, p_st2);

        // GEMM1: [N,128] x [256,128]^T -> [N,256]  (stats fused)
        {
            dim3 grid((2 * HH) / GBN, (NN + GBM - 1) / GBM);
            k_gemm_bf16<<<grid, 256>>>(p_xin, conv_w1 + (size_t)l * 2 * HH * HH,
                                       conv_b1 + (size_t)l * 2 * HH,
                                       nullptr, nullptr, p_hmid, p_st1, NN, 2 * HH, HH);
        }
        k_bnprep<<<1, 256>>>(p_st1, cbn_g + (size_t)l * 2 * HH,
                             cbn_b + (size_t)l * 2 * HH, p_ss1, 2 * HH);

        // GEMM2: [N,256] x [128,256]^T -> [N,128]  (BN+ReLU fused on input, stats fused)
        {
            dim3 grid(HH / GBN, (NN + GBM - 1) / GBM);
            k_gemm_bf16<<<grid, 256>>>(p_hmid, conv_w2 + (size_t)l * HH * 2 * HH,
                                       conv_b2 + (size_t)l * HH,
                                       p_ss1, p_ss1 + 2 * HH, p_hraw, p_st2, NN, HH, 2 * HH);
        }
        k_bnprep<<<1, 128>>>(p_st2, bn_g + (size_t)l * HH,
                             bn_b + (size_t)l * HH, p_ss2, HH);
    }

    // --- pool (+ final BN/ReLU) + head ---
    k_zero_f<<<(GG * HH + 255) / 256, 256>>>(p_pool, GG * HH);
    k_pool<<<(NN * 32 + 255) / 256, 256>>>(p_hraw, batch, p_ss2, p_ss2 + HH);
    k_head<<<GG, 256>>>(lstm_wih, lstm_bih, lstm_bhh, lin_w, lin_b, outp);
}

// round 4
// speedup vs baseline: 2.1574x; 1.2006x over previous
#include <cuda_runtime.h>
#include <cuda_bf16.h>
#include <math.h>
#include <stdint.h>

#define NN 50000
#define EE 640000
#define GG 256
#define INC 32
#define HH 128
#define LL 5
#define LH 64
#define OUTC 10
#define EPS_GEN 1e-7f

// ---------------- scratch (static device globals; no runtime alloc) ----------
__device__ float g_h[NN * HH];
__device__ float g_xin[NN * HH];
__device__ float g_hmid[NN * 2 * HH];
__device__ float g_hraw[NN * HH];
__device__ float g_cat[NN * 40];
__device__ int   g_deg[NN];
__device__ int   g_cursor[NN];
__device__ int   g_rowstart[NN + 1];
__device__ int   g_csr[EE];
__device__ float g_st1[512];
__device__ float g_st2[256];
__device__ float g_ss1[512];
__device__ float g_ss2[256];
__device__ float g_p[GG * HH];

// ---------------- utility kernels -------------------------------------------
__global__ void k_zero2_int(int* a, int* b, int n) {
    int i = blockIdx.x * blockDim.x + threadIdx.x;
    if (i < n) { a[i] = 0; b[i] = 0; }
}
__global__ void k_zero_f(float* a, int n) {
    int i = blockIdx.x * blockDim.x + threadIdx.x;
    if (i < n) a[i] = 0.f;
}
__global__ void k_zero_st(float* a, float* b) {
    int i = blockIdx.x * blockDim.x + threadIdx.x;
    if (i < 512) a[i] = 0.f;
    if (i < 256) b[i] = 0.f;
}

__global__ void k_hist(const int* __restrict__ dst) {
    int e = blockIdx.x * blockDim.x + threadIdx.x;
    if (e < EE) atomicAdd(&g_deg[dst[e]], 1);
}

__global__ void k_scan() {
    __shared__ int sh[1024];
    int t = threadIdx.x;
    int running = 0;
    for (int base = 0; base < NN; base += 1024) {
        int v = (base + t < NN) ? g_deg[base + t] : 0;
        sh[t] = v;
        __syncthreads();
        #pragma unroll
        for (int off = 1; off < 1024; off <<= 1) {
            int u = (t >= off) ? sh[t - off] : 0;
            __syncthreads();
            sh[t] += u;
            __syncthreads();
        }
        int incl = sh[t];
        if (base + t < NN) g_rowstart[base + t] = running + incl - v;
        int tot = sh[1023];
        __syncthreads();
        running += tot;
    }
    if (t == 0) g_rowstart[NN] = running;
}

__global__ void k_scatter(const int* __restrict__ src, const int* __restrict__ dst,
                          const int* __restrict__ attr) {
    int e = blockIdx.x * blockDim.x + threadIdx.x;
    if (e >= EE) return;
    int d = dst[e];
    int pos = atomicAdd(&g_cursor[d], 1);
    g_csr[g_rowstart[d] + pos] = (src[e] << 2) | (attr[e] & 3);
}

__global__ void k_cat(const float* __restrict__ x, const float* __restrict__ ncc) {
    int i = blockIdx.x * blockDim.x + threadIdx.x;
    if (i >= NN * 40) return;
    int n = i / 40, k = i - n * 40;
    g_cat[i] = (k < 32) ? x[n * 32 + k] : ncc[n * 8 + (k - 32)];
}

// ================= bf16 split-2, double-buffered pipelined GEMM ==============
// C[n,m] = sum_k A'[n,k] * W[m,k] + bias[m]
//   A'[n,k] = scl ? relu(A[n,k]*scl[k]+shf[k]) : A[n,k]
// optional stats: colsum -> stats[0:M), colsumsq -> stats[M:2M)
#define GBM 128
#define GBN 64
#define GBK 32
#define ASTR 40   // smem row stride in bf16 elems (80B: ldmatrix conflict-free)
#define APL (GBM * ASTR)
#define BPL (GBN * ASTR)

__device__ __forceinline__ void mma16(float* c, const uint32_t* a, const uint32_t* b) {
    asm volatile(
        "mma.sync.aligned.m16n8k16.row.col.f32.bf16.bf16.f32 "
        "{%0,%1,%2,%3}, {%4,%5,%6,%7}, {%8,%9}, {%0,%1,%2,%3};\n"
        : "+f"(c[0]), "+f"(c[1]), "+f"(c[2]), "+f"(c[3])
        : "r"(a[0]), "r"(a[1]), "r"(a[2]), "r"(a[3]), "r"(b[0]), "r"(b[1]));
}

__device__ __forceinline__ void split_pair(float x0, float x1,
                                           uint32_t& hi, uint32_t& lo) {
    __nv_bfloat16 h0 = __float2bfloat16(x0), h1 = __float2bfloat16(x1);
    float r0 = x0 - __bfloat162float(h0);
    float r1 = x1 - __bfloat162float(h1);
    __nv_bfloat16 l0 = __float2bfloat16(r0), l1 = __float2bfloat16(r1);
    hi = (uint32_t)*(uint16_t*)&h0 | ((uint32_t)*(uint16_t*)&h1 << 16);
    lo = (uint32_t)*(uint16_t*)&l0 | ((uint32_t)*(uint16_t*)&l1 << 16);
}

__global__ __launch_bounds__(256, 2) void k_gemm_bf16(
    const float* __restrict__ A, const float* __restrict__ W,
    const float* __restrict__ bias,
    const float* __restrict__ scl, const float* __restrict__ shf,
    float* __restrict__ C, float* __restrict__ stats,
    int nrows, int M, int K)
{
    // [buf][plane][...]
    __shared__ __align__(16) uint16_t As[2][2][APL];
    __shared__ __align__(16) uint16_t Bs[2][2][BPL];

    int tid = threadIdx.x, lane = tid & 31, wid = tid >> 5;
    int gid = lane >> 2, tig = lane & 3;
    int wm = wid & 3, wn = wid >> 2;
    int row0 = blockIdx.y * GBM, col0 = blockIdx.x * GBN;

    float acc[2][4][4];
    #pragma unroll
    for (int i = 0; i < 2; i++)
        #pragma unroll
        for (int j = 0; j < 4; j++)
            #pragma unroll
            for (int q = 0; q < 4; q++) acc[i][j][q] = 0.f;

    // staging indices
    int s_ar = tid >> 1;            // A tile row 0..127
    int s_ak = (tid & 1) * 16;      // 0 / 16
    int s_wr = tid >> 2;            // W tile row 0..63
    int s_wk = (tid & 3) * 8;       // 0,8,16,24
    int growA = row0 + s_ar;
    bool rokA = growA < nrows;
    const float* Arow = A + (size_t)growA * K;
    const float* Wrow = W + (size_t)(col0 + s_wr) * K;

    // ldmatrix per-lane offsets
    int l7 = lane & 7, l8 = (lane >> 3) & 1, l16 = lane >> 4;
    uint32_t as_smem = (uint32_t)__cvta_generic_to_shared(&As[0][0][0]);
    uint32_t bs_smem = (uint32_t)__cvta_generic_to_shared(&Bs[0][0][0]);
    uint32_t aoff[2], boff[2];
    #pragma unroll
    for (int i = 0; i < 2; i++)
        aoff[i] = ((wm * 32 + i * 16 + l7 + l8 * 8) * ASTR + l16 * 8) * 2;
    #pragma unroll
    for (int jp = 0; jp < 2; jp++)
        boff[jp] = ((wn * 32 + jp * 16 + l7 + l16 * 8) * ASTR + l8 * 8) * 2;

    int nT = (K + GBK - 1) / GBK;
    float vA[16], vB[8];

    // ---- load tile t into prefetch registers ----
    auto load_tile = [&](int t) {
        int kb = t * GBK;
        #pragma unroll
        for (int f = 0; f < 4; f++) {
            int kg = kb + s_ak + f * 4;
            float4 v = make_float4(0.f, 0.f, 0.f, 0.f);
            if (rokA && kg + 4 <= K) {
                v = *(const float4*)&Arow[kg];
                if (scl) {
                    v.x = fmaxf(fmaf(v.x, scl[kg + 0], shf[kg + 0]), 0.f);
                    v.y = fmaxf(fmaf(v.y, scl[kg + 1], shf[kg + 1]), 0.f);
                    v.z = fmaxf(fmaf(v.z, scl[kg + 2], shf[kg + 2]), 0.f);
                    v.w = fmaxf(fmaf(v.w, scl[kg + 3], shf[kg + 3]), 0.f);
                }
            }
            vA[f * 4 + 0] = v.x; vA[f * 4 + 1] = v.y;
            vA[f * 4 + 2] = v.z; vA[f * 4 + 3] = v.w;
        }
        #pragma unroll
        for (int f = 0; f < 2; f++) {
            int kg = kb + s_wk + f * 4;
            float4 v = make_float4(0.f, 0.f, 0.f, 0.f);
            if (kg + 4 <= K) v = *(const float4*)&Wrow[kg];
            vB[f * 4 + 0] = v.x; vB[f * 4 + 1] = v.y;
            vB[f * 4 + 2] = v.z; vB[f * 4 + 3] = v.w;
        }
    };
    // ---- convert prefetch registers, store into smem buffer b ----
    auto store_tile = [&](int b) {
        uint32_t hi[8], lo[8];
        #pragma unroll
        for (int e = 0; e < 8; e++) split_pair(vA[2 * e], vA[2 * e + 1], hi[e], lo[e]);
        uint32_t off = s_ar * ASTR + s_ak;
        *(uint4*)&As[b][0][off]     = make_uint4(hi[0], hi[1], hi[2], hi[3]);
        *(uint4*)&As[b][0][off + 8] = make_uint4(hi[4], hi[5], hi[6], hi[7]);
        *(uint4*)&As[b][1][off]     = make_uint4(lo[0], lo[1], lo[2], lo[3]);
        *(uint4*)&As[b][1][off + 8] = make_uint4(lo[4], lo[5], lo[6], lo[7]);
        uint32_t bhi[4], blo[4];
        #pragma unroll
        for (int e = 0; e < 4; e++) split_pair(vB[2 * e], vB[2 * e + 1], bhi[e], blo[e]);
        uint32_t woff = s_wr * ASTR + s_wk;
        *(uint4*)&Bs[b][0][woff] = make_uint4(bhi[0], bhi[1], bhi[2], bhi[3]);
        *(uint4*)&Bs[b][1][woff] = make_uint4(blo[0], blo[1], blo[2], blo[3]);
    };

    load_tile(0);
    store_tile(0);
    __syncthreads();

    for (int t = 0; t < nT; t++) {
        int cur = t & 1;
        bool more = (t + 1 < nT);
        if (more) load_tile(t + 1);

        uint32_t abase0 = as_smem + (uint32_t)(cur * 2 + 0) * (APL * 2);
        uint32_t abase1 = as_smem + (uint32_t)(cur * 2 + 1) * (APL * 2);
        uint32_t bbase0 = bs_smem + (uint32_t)(cur * 2 + 0) * (BPL * 2);
        uint32_t bbase1 = bs_smem + (uint32_t)(cur * 2 + 1) * (BPL * 2);

        #pragma unroll
        for (int ksx = 0; ksx < 2; ksx++) {
            uint32_t ksb = ksx * 32;
            uint32_t a[2][2][4];
            uint32_t b[2][4][2];
            #pragma unroll
            for (int i = 0; i < 2; i++) {
                asm volatile(
                    "ldmatrix.sync.aligned.m8n8.x4.shared.b16 {%0,%1,%2,%3}, [%4];"
                    : "=r"(a[0][i][0]), "=r"(a[0][i][1]),
                      "=r"(a[0][i][2]), "=r"(a[0][i][3])
                    : "r"(abase0 + aoff[i] + ksb));
                asm volatile(
                    "ldmatrix.sync.aligned.m8n8.x4.shared.b16 {%0,%1,%2,%3}, [%4];"
                    : "=r"(a[1][i][0]), "=r"(a[1][i][1]),
                      "=r"(a[1][i][2]), "=r"(a[1][i][3])
                    : "r"(abase1 + aoff[i] + ksb));
            }
            #pragma unroll
            for (int jp = 0; jp < 2; jp++) {
                asm volatile(
                    "ldmatrix.sync.aligned.m8n8.x4.shared.b16 {%0,%1,%2,%3}, [%4];"
                    : "=r"(b[0][jp * 2][0]), "=r"(b[0][jp * 2][1]),
                      "=r"(b[0][jp * 2 + 1][0]), "=r"(b[0][jp * 2 + 1][1])
                    : "r"(bbase0 + boff[jp] + ksb));
                asm volatile(
                    "ldmatrix.sync.aligned.m8n8.x4.shared.b16 {%0,%1,%2,%3}, [%4];"
                    : "=r"(b[1][jp * 2][0]), "=r"(b[1][jp * 2][1]),
                      "=r"(b[1][jp * 2 + 1][0]), "=r"(b[1][jp * 2 + 1][1])
                    : "r"(bbase1 + boff[jp] + ksb));
            }
            #pragma unroll
            for (int i = 0; i < 2; i++)
                #pragma unroll
                for (int j = 0; j < 4; j++) {
                    mma16(acc[i][j], a[0][i], b[0][j]);   // hi*hi
                    mma16(acc[i][j], a[0][i], b[1][j]);   // hi*lo
                    mma16(acc[i][j], a[1][i], b[0][j]);   // lo*hi
                }
        }
        if (more) store_tile(cur ^ 1);
        __syncthreads();
    }

    // ---- epilogue: bias, store, optional column stats ----
    #pragma unroll
    for (int i = 0; i < 2; i++)
        #pragma unroll
        for (int j = 0; j < 4; j++) {
            int c = col0 + wn * 32 + j * 8 + tig * 2;
            float2 b2 = *(const float2*)&bias[c];
            acc[i][j][0] += b2.x; acc[i][j][1] += b2.y;
            acc[i][j][2] += b2.x; acc[i][j][3] += b2.y;
        }
    #pragma unroll
    for (int i = 0; i < 2; i++) {
        int r = row0 + wm * 32 + i * 16 + gid;
        #pragma unroll
        for (int j = 0; j < 4; j++) {
            int c = col0 + wn * 32 + j * 8 + tig * 2;
            if (r < nrows) {
                float2 o = {acc[i][j][0], acc[i][j][1]};
                *(float2*)&C[(size_t)r * M + c] = o;
            }
            if (r + 8 < nrows) {
                float2 o = {acc[i][j][2], acc[i][j][3]};
                *(float2*)&C[(size_t)(r + 8) * M + c] = o;
            }
        }
    }
    if (stats) {
        #pragma unroll
        for (int j = 0; j < 4; j++)
            #pragma unroll
            for (int qc = 0; qc < 2; qc++) {
                float sv = 0.f, qv = 0.f;
                #pragma unroll
                for (int i = 0; i < 2; i++) {
                    int r = row0 + wm * 32 + i * 16 + gid;
                    if (r < nrows)     { float v = acc[i][j][qc];     sv += v; qv += v * v; }
                    if (r + 8 < nrows) { float v = acc[i][j][qc + 2]; sv += v; qv += v * v; }
                }
                #pragma unroll
                for (int o = 4; o < 32; o <<= 1) {
                    sv += __shfl_xor_sync(0xffffffffu, sv, o);
                    qv += __shfl_xor_sync(0xffffffffu, qv, o);
                }
                if (lane < 4) {
                    int c = col0 + wn * 32 + j * 8 + tig * 2 + qc;
                    atomicAdd(&stats[c], sv);
                    atomicAdd(&stats[M + c], qv);
                }
            }
    }
}

// BN prep: scale/shift from stats, then self-clean stats for the next layer.
__global__ void k_bnprep(float* __restrict__ stats,
                         const float* __restrict__ gam, const float* __restrict__ bet,
                         float* __restrict__ ss, int M) {
    int m = blockIdx.x * blockDim.x + threadIdx.x;
    if (m >= M) return;
    float invN = 1.f / (float)NN;
    float mu = stats[m] * invN;
    float var = stats[M + m] * invN - mu * mu;
    float sc = rsqrtf(var + 1e-5f) * gam[m];
    ss[m] = sc;
    ss[M + m] = bet[m] - mu * sc;
    stats[m] = 0.f;
    stats[M + m] = 0.f;
}

// ---------------- fused edge aggregation (+ BN/ReLU of input on the fly) ------
// softmax computed without max-subtraction (shift-invariant; messages bounded)
__device__ __forceinline__ void agg_step(float4 hv, float4 ev, float4 sc, float4 sh,
                                         bool bn, float* s, float* w) {
    if (bn) {
        hv.x = fmaxf(fmaf(hv.x, sc.x, sh.x), 0.f);
        hv.y = fmaxf(fmaf(hv.y, sc.y, sh.y), 0.f);
        hv.z = fmaxf(fmaf(hv.z, sc.z, sh.z), 0.f);
        hv.w = fmaxf(fmaf(hv.w, sc.w, sh.w), 0.f);
    }
    float msg[4];
    msg[0] = fmaxf(hv.x + ev.x, 0.f) + EPS_GEN;
    msg[1] = fmaxf(hv.y + ev.y, 0.f) + EPS_GEN;
    msg[2] = fmaxf(hv.z + ev.z, 0.f) + EPS_GEN;
    msg[3] = fmaxf(hv.w + ev.w, 0.f) + EPS_GEN;
    #pragma unroll
    for (int c = 0; c < 4; c++) {
        float e = __expf(msg[c]);
        s[c] += e;
        w[c] = fmaf(e, msg[c], w[c]);
    }
}

__global__ void k_agg(const float* __restrict__ h, const float* __restrict__ eemb,
                      const float* __restrict__ scl, const float* __restrict__ shf,
                      float* __restrict__ out) {
    int warp = (blockIdx.x * blockDim.x + threadIdx.x) >> 5;
    int lane = threadIdx.x & 31;
    if (warp >= NN) return;
    int n = warp;
    int beg = g_rowstart[n], end = g_rowstart[n + 1];
    int co = lane * 4;
    bool bn = (scl != nullptr);
    float4 sc = make_float4(1.f, 1.f, 1.f, 1.f), sh = make_float4(0.f, 0.f, 0.f, 0.f);
    if (bn) { sc = *(const float4*)&scl[co]; sh = *(const float4*)&shf[co]; }
    float s[4] = {0.f, 0.f, 0.f, 0.f};
    float w[4] = {0.f, 0.f, 0.f, 0.f};
    int j = beg;
    for (; j + 2 <= end; j += 2) {
        int p0 = __ldg(&g_csr[j]);
        int p1 = __ldg(&g_csr[j + 1]);
        float4 hv0 = *(const float4*)&h[(size_t)(p0 >> 2) * HH + co];
        float4 hv1 = *(const float4*)&h[(size_t)(p1 >> 2) * HH + co];
        float4 ev0 = *(const float4*)&eemb[(p0 & 3) * HH + co];
        float4 ev1 = *(const float4*)&eemb[(p1 & 3) * HH + co];
        agg_step(hv0, ev0, sc, sh, bn, s, w);
        agg_step(hv1, ev1, sc, sh, bn, s, w);
    }
    if (j < end) {
        int p0 = __ldg(&g_csr[j]);
        float4 hv0 = *(const float4*)&h[(size_t)(p0 >> 2) * HH + co];
        float4 ev0 = *(const float4*)&eemb[(p0 & 3) * HH + co];
        agg_step(hv0, ev0, sc, sh, bn, s, w);
    }
    float4 hn = *(const float4*)&h[(size_t)n * HH + co];
    if (bn) {
        hn.x = fmaxf(fmaf(hn.x, sc.x, sh.x), 0.f);
        hn.y = fmaxf(fmaf(hn.y, sc.y, sh.y), 0.f);
        hn.z = fmaxf(fmaf(hn.z, sc.z, sh.z), 0.f);
        hn.w = fmaxf(fmaf(hn.w, sc.w, sh.w), 0.f);
    }
    bool has = end > beg;
    float4 o;
    o.x = (has ? w[0] / s[0] : 0.f) + hn.x;
    o.y = (has ? w[1] / s[1] : 0.f) + hn.y;
    o.z = (has ? w[2] / s[2] : 0.f) + hn.z;
    o.w = (has ? w[3] / s[3] : 0.f) + hn.w;
    *(float4*)&out[(size_t)n * HH + co] = o;
}

// ---------------- pooling (applies final-layer BN+ReLU on the fly) ------------
__global__ void k_pool(const float* __restrict__ h, const int* __restrict__ batch,
                       const float* __restrict__ scl, const float* __restrict__ shf) {
    int i = blockIdx.x * blockDim.x + threadIdx.x;
    if (i >= NN * 32) return;
    int n = i >> 5;
    int lane = i & 31;
    int co = lane * 4;
    int g = batch[n];
    float4 v = *(const float4*)&h[(size_t)n * HH + co];
    float4 sc = *(const float4*)&scl[co];
    float4 sh = *(const float4*)&shf[co];
    v.x = fmaxf(fmaf(v.x, sc.x, sh.x), 0.f);
    v.y = fmaxf(fmaf(v.y, sc.y, sh.y), 0.f);
    v.z = fmaxf(fmaf(v.z, sc.z, sh.z), 0.f);
    v.w = fmaxf(fmaf(v.w, sc.w, sh.w), 0.f);
    float* dst = &g_p[(size_t)g * HH + co];
    atomicAdd(dst + 0, v.x);
    atomicAdd(dst + 1, v.y);
    atomicAdd(dst + 2, v.z);
    atomicAdd(dst + 3, v.w);
}

// ---------------- head: LSTM (1 step, h0=c0=0) + final linear ------------------
__device__ __forceinline__ float sigm(float x) { return 1.f / (1.f + __expf(-x)); }

__global__ void k_head(const float* __restrict__ wih, const float* __restrict__ bih,
                       const float* __restrict__ bhh, const float* __restrict__ linw,
                       const float* __restrict__ linb, float* __restrict__ out) {
    __shared__ float ps[HH];
    __shared__ float gs[4 * LH];
    __shared__ float hh[LH];
    int g = blockIdx.x;
    int t = threadIdx.x;       // 256 threads
    if (t < HH) ps[t] = g_p[(size_t)g * HH + t];
    __syncthreads();
    {
        float acc = bih[t] + bhh[t];
        const float* wr = &wih[(size_t)t * HH];
        #pragma unroll 8
        for (int k = 0; k < HH; k++) acc = fmaf(ps[k], wr[k], acc);
        gs[t] = acc;
    }
    __syncthreads();
    if (t < LH) {
        float ig = gs[t];
        float gg = gs[t + 2 * LH];
        float og = gs[t + 3 * LH];
        float c = sigm(ig) * tanhf(gg);
        hh[t] = sigm(og) * tanhf(c);
    }
    __syncthreads();
    if (t < OUTC) {
        float acc = linb[t];
        const float* wr = &linw[(size_t)t * LH];
        #pragma unroll
        for (int k = 0; k < LH; k++) acc = fmaf(hh[k], wr[k], acc);
        out[(size_t)g * OUTC + t] = acc;
    }
}

// ---------------- launch -------------------------------------------------------
extern "C" void kernel_launch(void* const* d_in, const int* in_sizes, int n_in,
                              void* d_out, int out_size) {
    const float* x        = (const float*)d_in[0];
    const float* ncc      = (const float*)d_in[1];
    const int*   eidx     = (const int*)d_in[2];
    const int*   eattr    = (const int*)d_in[3];
    const int*   batch    = (const int*)d_in[4];
    const float* fc_w     = (const float*)d_in[5];
    const float* fc_b     = (const float*)d_in[6];
    const float* edge_emb = (const float*)d_in[7];
    const float* conv_w1  = (const float*)d_in[8];
    const float* conv_b1  = (const float*)d_in[9];
    const float* cbn_g    = (const float*)d_in[10];
    const float* cbn_b    = (const float*)d_in[11];
    const float* conv_w2  = (const float*)d_in[12];
    const float* conv_b2  = (const float*)d_in[13];
    const float* bn_g     = (const float*)d_in[14];
    const float* bn_b     = (const float*)d_in[15];
    const float* lstm_wih = (const float*)d_in[16];
    const float* lstm_whh = (const float*)d_in[17];  // unused (h0 = 0)
    const float* lstm_bih = (const float*)d_in[18];
    const float* lstm_bhh = (const float*)d_in[19];
    const float* lin_w    = (const float*)d_in[20];
    const float* lin_b    = (const float*)d_in[21];
    (void)lstm_whh; (void)n_in; (void)in_sizes; (void)out_size;
    float* outp = (float*)d_out;

    const int* src = eidx;
    const int* dst = eidx + EE;

    int *p_deg, *p_cursor;
    float *p_h, *p_xin, *p_hmid, *p_hraw, *p_cat, *p_st1, *p_st2, *p_ss1, *p_ss2, *p_pool;
    cudaGetSymbolAddress((void**)&p_deg, g_deg);
    cudaGetSymbolAddress((void**)&p_cursor, g_cursor);
    cudaGetSymbolAddress((void**)&p_h, g_h);
    cudaGetSymbolAddress((void**)&p_xin, g_xin);
    cudaGetSymbolAddress((void**)&p_hmid, g_hmid);
    cudaGetSymbolAddress((void**)&p_hraw, g_hraw);
    cudaGetSymbolAddress((void**)&p_cat, g_cat);
    cudaGetSymbolAddress((void**)&p_st1, g_st1);
    cudaGetSymbolAddress((void**)&p_st2, g_st2);
    cudaGetSymbolAddress((void**)&p_ss1, g_ss1);
    cudaGetSymbolAddress((void**)&p_ss2, g_ss2);
    cudaGetSymbolAddress((void**)&p_pool, g_p);

    // --- CSR build ---
    k_zero2_int<<<(NN + 255) / 256, 256>>>(p_deg, p_cursor, NN);
    k_hist<<<(EE + 255) / 256, 256>>>(dst);
    k_scan<<<1, 1024>>>();
    k_scatter<<<(EE + 255) / 256, 256>>>(src, dst, eattr);

    // --- initial FC: h = concat(x,ncc) @ fc_w^T + fc_b ---
    k_cat<<<(NN * 40 + 255) / 256, 256>>>(x, ncc);
    {
        dim3 grid(HH / GBN, (NN + GBM - 1) / GBM);
        k_gemm_bf16<<<grid, 256>>>(p_cat, fc_w, fc_b, nullptr, nullptr,
                                   p_h, nullptr, NN, HH, 40);
    }

    // one-time stats zero (k_bnprep self-cleans afterwards)
    k_zero_st<<<2, 256>>>(p_st1, p_st2);

    // --- layers ---
    for (int l = 0; l < LL; l++) {
        const float* hin = (l == 0) ? p_h : p_hraw;
        const float* asc = (l == 0) ? nullptr : p_ss2;
        const float* ash = (l == 0) ? nullptr : p_ss2 + HH;
        k_agg<<<(NN * 32 + 255) / 256, 256>>>(hin, edge_emb, asc, ash, p_xin);

        // GEMM1: [N,128] x [256,128]^T -> [N,256]  (stats fused)
        {
            dim3 grid((2 * HH) / GBN, (NN + GBM - 1) / GBM);
            k_gemm_bf16<<<grid, 256>>>(p_xin, conv_w1 + (size_t)l * 2 * HH * HH,
                                       conv_b1 + (size_t)l * 2 * HH,
                                       nullptr, nullptr, p_hmid, p_st1, NN, 2 * HH, HH);
        }
        k_bnprep<<<1, 256>>>(p_st1, cbn_g + (size_t)l * 2 * HH,
                             cbn_b + (size_t)l * 2 * HH, p_ss1, 2 * HH);

        // GEMM2: [N,256] x [128,256]^T -> [N,128]  (BN+ReLU fused on input, stats fused)
        {
            dim3 grid(HH / GBN, (NN + GBM - 1) / GBM);
            k_gemm_bf16<<<grid, 256>>>(p_hmid, conv_w2 + (size_t)l * HH * 2 * HH,
                                       conv_b2 + (size_t)l * HH,
                                       p_ss1, p_ss1 + 2 * HH, p_hraw, p_st2, NN, HH, 2 * HH);
        }
        k_bnprep<<<1, 128>>>(p_st2, bn_g + (size_t)l * HH,
                             bn_b + (size_t)l * HH, p_ss2, HH);
    }

    // --- pool (+ final BN/ReLU) + head ---
    k_zero_f<<<(GG * HH + 255) / 256, 256>>>(p_pool, GG * HH);
    k_pool<<<(NN * 32 + 255) / 256, 256>>>(p_hraw, batch, p_ss2, p_ss2 + HH);
    k_head<<<GG, 256>>>(lstm_wih, lstm_bih, lstm_bhh, lin_w, lin_b, outp);
}